// round 13
// baseline (speedup 1.0000x reference)
#include <cuda_runtime.h>
#include <math.h>

#define BN 4096      // total nodes (B*N)
#define NN 1024      // nodes per graph
#define KK 128       // neighbours
#define DD 32        // feature dim
#define EH 130       // edge hidden
#define EHP 132      // padded edge hidden (mult of 4)

typedef unsigned long long u64;

__device__ float g_feats[2][BN*DD];
__device__ float g_coors[2][BN*2];
__device__ int   g_idx[BN*KK];
__device__ float g_dist[BN*KK];
__device__ float g_A[BN*EHP];
__device__ float g_Bv[BN*EHP];
__device__ float g_msum[BN*DD];

__device__ __forceinline__ float lrelu(float x){ return fmaxf(x, 0.1f*x); }

__device__ __forceinline__ u64 pk2(float lo, float hi){
    u64 r; asm("mov.b64 %0, {%1,%2};" : "=l"(r) : "f"(lo), "f"(hi)); return r;
}
__device__ __forceinline__ float2 upk2(u64 v){
    float2 f; asm("mov.b64 {%0,%1}, %2;" : "=f"(f.x), "=f"(f.y) : "l"(v)); return f;
}
__device__ __forceinline__ u64 fma2_(u64 a, u64 b, u64 c){
    u64 d; asm("fma.rn.f32x2 %0, %1, %2, %3;" : "=l"(d) : "l"(a), "l"(b), "l"(c)); return d;
}
__device__ __forceinline__ u64 add2_(u64 a, u64 b){
    u64 d; asm("add.rn.f32x2 %0, %1, %2;" : "=l"(d) : "l"(a), "l"(b)); return d;
}
__device__ __forceinline__ u64 mul2_(u64 a, u64 b){
    u64 d; asm("mul.rn.f32x2 %0, %1, %2;" : "=l"(d) : "l"(a), "l"(b)); return d;
}

// ================= knn body: TWO nodes per block, shared phases (256 thr) =================
// Per-node selection logic identical to the proven single-node radix select;
// both nodes' work interleaved so every barrier serves both.
__device__ void knn_body2(int gi0, int cur){
    __shared__ float2 sc[NN];
    __shared__ unsigned int hist[2][1024];
    __shared__ u64 cand[2][NN];
    __shared__ unsigned int sWarp[2][8][2];
    __shared__ unsigned int sScan[2][8];
    __shared__ unsigned int sT[2], sNeed[2];

    int t = threadIdx.x;
    int b = gi0 >> 10;
    int il0 = gi0 & 1023;
    const float2* C = (const float2*)(g_coors[cur]) + b*NN;
    for (int x = t; x < NN; x += 256) sc[x] = C[x];
    for (int x = t; x < 2048; x += 256) hist[0][x] = 0u;   // clears both planes
    __syncthreads();

    float2 ci0 = sc[il0], ci1 = sc[il0 + 1];
    u64 key[2][4]; unsigned bin[2][4];
    #pragma unroll
    for (int r = 0; r < 4; r++){
        int x = t + 256*r;
        float2 p = sc[x];
        float dx0 = ci0.x - p.x, dy0 = ci0.y - p.y;
        float dx1 = ci1.x - p.x, dy1 = ci1.y - p.y;
        float d0 = dx0*dx0 + dy0*dy0;
        float d1 = dx1*dx1 + dy1*dy1;
        unsigned db0 = __float_as_uint(d0), db1 = __float_as_uint(d1);
        key[0][r] = ((u64)db0 << 32) | (unsigned)x;
        key[1][r] = ((u64)db1 << 32) | (unsigned)x;
        bin[0][r] = min(db0 >> 22, 1023u);
        bin[1][r] = min(db1 >> 22, 1023u);
        atomicAdd(&hist[0][bin[0][r]], 1u);
        atomicAdd(&hist[1][bin[1][r]], 1u);
    }
    __syncthreads();

    unsigned lane = t & 31, w = t >> 5;
    // two independent scans over 1024 bins each, shared shuffles/barriers
    unsigned local0 = hist[0][4*t] + hist[0][4*t+1] + hist[0][4*t+2] + hist[0][4*t+3];
    unsigned local1 = hist[1][4*t] + hist[1][4*t+1] + hist[1][4*t+2] + hist[1][4*t+3];
    unsigned v0 = local0, v1 = local1;
    #pragma unroll
    for (int off = 1; off < 32; off <<= 1){
        unsigned n0 = __shfl_up_sync(0xffffffffu, v0, off);
        unsigned n1 = __shfl_up_sync(0xffffffffu, v1, off);
        if (lane >= off){ v0 += n0; v1 += n1; }
    }
    if (lane == 31){ sScan[0][w] = v0; sScan[1][w] = v1; }
    __syncthreads();
    unsigned wb0 = 0, wb1 = 0;
    #pragma unroll
    for (int i = 0; i < 8; i++) if (i < (int)w){ wb0 += sScan[0][i]; wb1 += sScan[1][i]; }
    unsigned run0 = wb0 + v0 - local0;
    unsigned run1 = wb1 + v1 - local1;
    #pragma unroll
    for (int q = 0; q < 4; q++){
        unsigned h0 = hist[0][4*t + q], h1 = hist[1][4*t + q];
        if (run0 <= 127u && run0 + h0 > 127u){ sT[0] = 4*t + q; sNeed[0] = 128u - run0; }
        if (run1 <= 127u && run1 + h1 > 127u){ sT[1] = 4*t + q; sNeed[1] = 128u - run1; }
        run0 += h0; run1 += h1;
    }
    __syncthreads();
    unsigned T0 = sT[0], T1 = sT[1];

    // deterministic compaction, both nodes per round
    unsigned winb[2] = {0u, 0u}, candb[2] = {0u, 0u};
    unsigned ltmask = (1u << lane) - 1u;
    #pragma unroll
    for (int r = 0; r < 4; r++){
        bool win0 = bin[0][r] < T0, cd0 = bin[0][r] == T0;
        bool win1 = bin[1][r] < T1, cd1 = bin[1][r] == T1;
        unsigned mw0 = __ballot_sync(0xffffffffu, win0);
        unsigned mc0 = __ballot_sync(0xffffffffu, cd0);
        unsigned mw1 = __ballot_sync(0xffffffffu, win1);
        unsigned mc1 = __ballot_sync(0xffffffffu, cd1);
        if (lane == 0){
            sWarp[0][w][0] = __popc(mw0); sWarp[0][w][1] = __popc(mc0);
            sWarp[1][w][0] = __popc(mw1); sWarp[1][w][1] = __popc(mc1);
        }
        __syncthreads();
        unsigned bw0 = winb[0], bc0 = candb[0], tw0 = 0, tc0 = 0;
        unsigned bw1 = winb[1], bc1 = candb[1], tw1 = 0, tc1 = 0;
        #pragma unroll
        for (int i = 0; i < 8; i++){
            unsigned a0 = sWarp[0][i][0], c0 = sWarp[0][i][1];
            unsigned a1 = sWarp[1][i][0], c1 = sWarp[1][i][1];
            if (i < (int)w){ bw0 += a0; bc0 += c0; bw1 += a1; bc1 += c1; }
            tw0 += a0; tc0 += c0; tw1 += a1; tc1 += c1;
        }
        if (win0){
            unsigned pos = bw0 + __popc(mw0 & ltmask);
            g_idx [gi0*KK + pos] = (int)(key[0][r] & 0xffffffffull);
            g_dist[gi0*KK + pos] = __uint_as_float((unsigned)(key[0][r] >> 32));
        }
        if (cd0){
            unsigned pos = bc0 + __popc(mc0 & ltmask);
            cand[0][pos] = key[0][r];
        }
        if (win1){
            unsigned pos = bw1 + __popc(mw1 & ltmask);
            g_idx [(gi0+1)*KK + pos] = (int)(key[1][r] & 0xffffffffull);
            g_dist[(gi0+1)*KK + pos] = __uint_as_float((unsigned)(key[1][r] >> 32));
        }
        if (cd1){
            unsigned pos = bc1 + __popc(mc1 & ltmask);
            cand[1][pos] = key[1][r];
        }
        winb[0] += tw0; candb[0] += tc0;
        winb[1] += tw1; candb[1] += tc1;
        __syncthreads();
    }

    // joint bitonic over both candidate sets (shared barriers, P = max)
    unsigned cnt0 = candb[0], cnt1 = candb[1];
    unsigned cmax = cnt0 > cnt1 ? cnt0 : cnt1;
    unsigned P = 2; while (P < cmax) P <<= 1;
    for (unsigned x = cnt0 + t; x < P; x += 256) cand[0][x] = 0xffffffffffffffffull;
    for (unsigned x = cnt1 + t; x < P; x += 256) cand[1][x] = 0xffffffffffffffffull;
    __syncthreads();
    for (unsigned k = 2; k <= P; k <<= 1){
        for (unsigned j = k >> 1; j > 0; j >>= 1){
            for (unsigned x = t; x < P; x += 256){
                unsigned ixj = x ^ j;
                if (ixj > x){
                    bool up = (x & k) == 0;
                    u64 a0 = cand[0][x], b0 = cand[0][ixj];
                    if ((a0 > b0) == up){ cand[0][x] = b0; cand[0][ixj] = a0; }
                    u64 a1 = cand[1][x], b1 = cand[1][ixj];
                    if ((a1 > b1) == up){ cand[1][x] = b1; cand[1][ixj] = a1; }
                }
            }
            __syncthreads();
        }
    }
    if (t < sNeed[0]){
        u64 kv = cand[0][t];
        unsigned pos = winb[0] + t;
        g_idx [gi0*KK + pos] = (int)(kv & 0xffffffffull);
        g_dist[gi0*KK + pos] = __uint_as_float((unsigned)(kv >> 32));
    }
    if (t < sNeed[1]){
        u64 kv = cand[1][t];
        unsigned pos = winb[1] + t;
        g_idx [(gi0+1)*KK + pos] = (int)(kv & 0xffffffffull);
        g_dist[(gi0+1)*KK + pos] = __uint_as_float((unsigned)(kv >> 32));
    }
}

// ================= pre body: A/Bv projections, 2 nodes x 128 threads =================
__device__ __forceinline__ void pre_body(int gi, int n, int tn, const float ff[2][DD],
                                         const float* __restrict__ e1w,
                                         const float* __restrict__ e1b){
    for (int u = tn; u < EHP; u += 128){
        float a = 0.f, bv = 0.f;
        if (u < EH){
            a = e1b[u];
            #pragma unroll
            for (int r = 0; r < DD; r++){
                float fr = ff[n][r];
                a  += fr * e1w[r*EH + u];
                bv += fr * e1w[(DD + r)*EH + u];
            }
        }
        g_A [gi*EHP + u] = a;
        g_Bv[gi*EHP + u] = bv;
    }
}

// ================= embed + pre body (2 nodes x 128 threads) =================
__device__ void embed_pre_body(int pair,
                               const float* __restrict__ feat,
                               const float* __restrict__ ew, const float* __restrict__ eb,
                               const float* __restrict__ e1w, const float* __restrict__ e1b){
    __shared__ float fin[2][DD], ff[2][DD];
    int t = threadIdx.x;
    int n = t >> 7, tn = t & 127;
    int gi = pair*2 + n;
    if (tn < DD) fin[n][tn] = feat[gi*DD + tn];
    __syncthreads();
    if (tn < DD){
        float a = eb[tn];
        #pragma unroll
        for (int r = 0; r < DD; r++) a += fin[n][r]*ew[r*DD + tn];
        float o = lrelu(a);
        g_feats[0][gi*DD + tn] = o;
        ff[n][tn] = o;
    }
    __syncthreads();
    pre_body(gi, n, tn, ff, e1w, e1b);
}

// ================= node MLP + residual (+pre of next layer), 2 nodes x 128 threads =================
__device__ void node_pre_body(int pair, int cur, int last, float* __restrict__ dout,
                              const float* __restrict__ n1w, const float* __restrict__ n1b,
                              const float* __restrict__ n2w, const float* __restrict__ n2b,
                              const float* __restrict__ e1w, const float* __restrict__ e1b){
    __shared__ float in[2][2*DD], h[2][2*DD], ff[2][DD];
    int t = threadIdx.x;
    int n = t >> 7, tn = t & 127;
    int gi = pair*2 + n;
    if (tn < 2*DD)
        in[n][tn] = (tn < DD) ? g_feats[cur][gi*DD + tn] : g_msum[gi*DD + (tn - DD)];
    __syncthreads();
    if (tn < 2*DD){
        float a = n1b[tn];
        #pragma unroll
        for (int r = 0; r < 2*DD; r++) a += in[n][r]*n1w[r*64 + tn];
        h[n][tn] = lrelu(a);
    }
    __syncthreads();
    if (tn < DD){
        float o = n2b[tn];
        #pragma unroll
        for (int r = 0; r < 2*DD; r++) o += h[n][r]*n2w[r*DD + tn];
        o += in[n][tn];
        if (last) dout[gi*DD + tn] = o;
        else { g_feats[cur^1][gi*DD + tn] = o; ff[n][tn] = o; }
    }
    if (last) return;                  // uniform across block
    __syncthreads();
    pre_body(gi, n, tn, ff, e1w, e1b);
}

// ================= fused launchers =================
// blocks [0,BN/2): knn pair; blocks [BN/2, BN): embed_pre pair
__global__ void __launch_bounds__(256)
embed_knn_kernel(int knnCur,
                 const float* __restrict__ feat,
                 const float* __restrict__ ew, const float* __restrict__ eb,
                 const float* __restrict__ e1w, const float* __restrict__ e1b){
    if (blockIdx.x < BN/2) knn_body2(blockIdx.x*2, knnCur);
    else embed_pre_body(blockIdx.x - BN/2, feat, ew, eb, e1w, e1b);
}

// blocks [0,BN/2): knn pair; blocks [BN/2, BN): node_pre pair
__global__ void __launch_bounds__(256)
node_knn_kernel(int npCur, int knnCur,
                const float* __restrict__ n1w, const float* __restrict__ n1b,
                const float* __restrict__ n2w, const float* __restrict__ n2b,
                const float* __restrict__ e1w, const float* __restrict__ e1b){
    if (blockIdx.x < BN/2) knn_body2(blockIdx.x*2, knnCur);
    else node_pre_body(blockIdx.x - BN/2, npCur, 0, (float*)0, n1w, n1b, n2w, n2b, e1w, e1b);
}

// final node MLP only (writes d_out)
__global__ void __launch_bounds__(256)
node_last_kernel(int cur, float* __restrict__ dout,
                 const float* __restrict__ n1w, const float* __restrict__ n1b,
                 const float* __restrict__ n2w, const float* __restrict__ n2b){
    node_pre_body(blockIdx.x, cur, 1, dout, n1w, n1b, n2w, n2b, (const float*)0, (const float*)0);
}

// ---------------- edge kernel: R8 known-good (4 nodes/block, 4 edges/thread) ----------------
__global__ void __launch_bounds__(128)
edge_kernel(int cur,
            const float* __restrict__ e1w, const float* __restrict__ e2w,
            const float* __restrict__ e2b, const float* __restrict__ gw,
            const float* __restrict__ gb,  const float* __restrict__ c1w,
            const float* __restrict__ c1b, const float* __restrict__ c2w,
            const float* __restrict__ c2b, const float* __restrict__ scl){
    __shared__ __align__(16) float sW2[EHP*DD];     // e2 weights [u][dd]
    __shared__ __align__(16) float sC1t[KK*36];     // c1 transposed [v][dd], stride 36
    __shared__ __align__(16) float sA[4][EHP];
    __shared__ __align__(16) float sW1c[EHP];
    __shared__ __align__(16) float sC2[KK];
    __shared__ __align__(16) float sC1b[KK];
    __shared__ __align__(16) float sGw[DD];
    __shared__ __align__(16) float sE2b[DD];

    int t = threadIdx.x;
    int w = t >> 5;                    // warp = node within block
    int lane = t & 31;
    int gi = blockIdx.x*4 + w;
    int b = gi >> 10;

    for (int x = t; x < EHP*DD; x += 128) sW2[x] = (x < EH*DD) ? e2w[x] : 0.f;
    for (int x = t; x < DD*KK; x += 128){ int dd = x >> 7, v = x & 127; sC1t[v*36 + dd] = c1w[x]; }
    for (int x = t; x < 4*EHP; x += 128){
        int n = x / EHP, u = x - n*EHP;
        sA[n][u] = g_A[(blockIdx.x*4 + n)*EHP + u];
    }
    for (int x = t; x < EHP; x += 128) sW1c[x] = (x < EH) ? e1w[64*EH + x] : 0.f;
    if (t < KK){ sC2[t] = c2w[t]; sC1b[t] = c1b[t]; }
    if (t < DD){ sGw[t] = gw[t]; sE2b[t] = e2b[t]; }
    __syncthreads();

    int   j[4]; float d[4];
    #pragma unroll
    for (int q = 0; q < 4; q++){
        j[q] = g_idx [gi*KK + lane + 32*q];
        d[q] = g_dist[gi*KK + lane + 32*q];
    }
    const float4* bvP[4];
    #pragma unroll
    for (int q = 0; q < 4; q++)
        bvP[q] = (const float4*)(g_Bv + (size_t)(b*NN + j[q])*EHP);

    const float4* a4p = (const float4*)(sA[w]);
    const float4* w4p = (const float4*)(sW1c);
    const u64* gw2 = (const u64*)sGw;

    u64 m[4][16];
    {
        const u64* b2 = (const u64*)sE2b;
        #pragma unroll
        for (int q = 0; q < 4; q++)
            #pragma unroll
            for (int i = 0; i < 16; i++) m[q][i] = b2[i];
    }

    // software-pipelined main loop
    float4 bvCur[4];
    #pragma unroll
    for (int q = 0; q < 4; q++) bvCur[q] = bvP[q][0];

    #pragma unroll 1
    for (int g = 0; g < EHP/4; g++){
        float4 bvNext[4];
        if (g + 1 < EHP/4){
            #pragma unroll
            for (int q = 0; q < 4; q++) bvNext[q] = bvP[q][g+1];
        }
        float4 aa = a4p[g], wc = w4p[g];
        float av[4] = {aa.x, aa.y, aa.z, aa.w};
        float wv[4] = {wc.x, wc.y, wc.z, wc.w};
        float bv[4][4];
        #pragma unroll
        for (int q = 0; q < 4; q++){
            bv[q][0] = bvCur[q].x; bv[q][1] = bvCur[q].y;
            bv[q][2] = bvCur[q].z; bv[q][3] = bvCur[q].w;
        }
        #pragma unroll
        for (int s = 0; s < 4; s++){
            int u = 4*g + s;
            u64 h2[4];
            #pragma unroll
            for (int q = 0; q < 4; q++){
                float h = lrelu(fmaf(d[q], wv[s], av[s]) + bv[q][s]);
                h2[q] = pk2(h, h);
            }
            const ulonglong2* w2 = (const ulonglong2*)(sW2 + u*DD);
            #pragma unroll
            for (int k = 0; k < 8; k++){
                ulonglong2 ww = w2[k];
                #pragma unroll
                for (int q = 0; q < 4; q++){
                    m[q][2*k]   = fma2_(h2[q], ww.x, m[q][2*k]);
                    m[q][2*k+1] = fma2_(h2[q], ww.y, m[q][2*k+1]);
                }
            }
        }
        #pragma unroll
        for (int q = 0; q < 4; q++) bvCur[q] = bvNext[q];
    }

    // lrelu on messages
    #pragma unroll
    for (int q = 0; q < 4; q++)
        #pragma unroll
        for (int i = 0; i < 16; i++){
            float2 f = upk2(m[q][i]);
            m[q][i] = pk2(lrelu(f.x), lrelu(f.y));
        }

    // soft-edge gates
    float gb0 = gb[0];
    {
        u64 acc[4] = {0ull,0ull,0ull,0ull};
        #pragma unroll
        for (int i = 0; i < 16; i++){
            u64 gwv = gw2[i];
            #pragma unroll
            for (int q = 0; q < 4; q++) acc[q] = fma2_(m[q][i], gwv, acc[q]);
        }
        #pragma unroll
        for (int q = 0; q < 4; q++){
            float2 a = upk2(acc[q]);
            float sg = 1.f/(1.f + expf(-(gb0 + a.x + a.y)));
            u64 sg2 = pk2(sg, sg);
            #pragma unroll
            for (int i = 0; i < 16; i++) m[q][i] = mul2_(m[q][i], sg2);
        }
    }

    // coors MLP -> per-edge scalar weight; 2 c1 rows per iteration for ILP
    float c2b0 = c2b[0];
    float cw[4] = {c2b0, c2b0, c2b0, c2b0};
    #pragma unroll 1
    for (int vp = 0; vp < KK/2; vp++){
        const ulonglong2* ccA = (const ulonglong2*)(sC1t + (2*vp)*36);
        const ulonglong2* ccB = (const ulonglong2*)(sC1t + (2*vp+1)*36);
        u64 sa[4] = {0ull,0ull,0ull,0ull};
        u64 sb[4] = {0ull,0ull,0ull,0ull};
        #pragma unroll
        for (int k = 0; k < 8; k++){
            ulonglong2 wa = ccA[k], wb = ccB[k];
            #pragma unroll
            for (int q = 0; q < 4; q++){
                sa[q] = fma2_(m[q][2*k],   wa.x, sa[q]);
                sa[q] = fma2_(m[q][2*k+1], wa.y, sa[q]);
                sb[q] = fma2_(m[q][2*k],   wb.x, sb[q]);
                sb[q] = fma2_(m[q][2*k+1], wb.y, sb[q]);
            }
        }
        float2 cb2 = ((const float2*)sC1b)[vp];
        float2 c22 = ((const float2*)sC2)[vp];
        #pragma unroll
        for (int q = 0; q < 4; q++){
            float2 fa = upk2(sa[q]), fb = upk2(sb[q]);
            cw[q] += lrelu(cb2.x + fa.x + fa.y)*c22.x;
            cw[q] += lrelu(cb2.y + fb.x + fb.y)*c22.y;
        }
    }

    // coordinate contributions
    const float2* Cg = (const float2*)(g_coors[cur]);
    float2 ci = Cg[gi];
    float sscl = scl[0];
    float cx = 0.f, cy = 0.f;
    #pragma unroll
    for (int q = 0; q < 4; q++){
        float2 cj = Cg[b*NN + j[q]];
        float rx = ci.x - cj.x, ry = ci.y - cj.y;
        float nm = fmaxf(sqrtf(rx*rx + ry*ry), 1e-8f);
        float ss = sscl/nm;
        cx += cw[q]*(rx*ss);
        cy += cw[q]*(ry*ss);
    }

    // warp-level reduction (node fully inside this warp)
    u64 mt[16];
    #pragma unroll
    for (int i = 0; i < 16; i++)
        mt[i] = add2_(add2_(m[0][i], m[1][i]), add2_(m[2][i], m[3][i]));
    u64 cp = pk2(cx, cy);
    #pragma unroll
    for (int off = 16; off > 0; off >>= 1){
        #pragma unroll
        for (int i = 0; i < 16; i++)
            mt[i] = add2_(mt[i], __shfl_xor_sync(0xffffffffu, mt[i], off));
        cp = add2_(cp, __shfl_xor_sync(0xffffffffu, cp, off));
    }
    if (lane < 16)
        ((u64*)(g_msum + (size_t)gi*DD))[lane] = mt[lane];
    if (lane == 0){
        float2 cf = upk2(cp);
        ((float2*)g_coors[cur^1])[gi] = make_float2(ci.x + cf.x, ci.y + cf.y);
    }
}

extern "C" void kernel_launch(void* const* d_in, const int* in_sizes, int n_in,
                              void* d_out, int out_size){
    const float* feat = (const float*)d_in[0];
    const float* coor = (const float*)d_in[1];
    // d_in[2] = batch (equal-size graphs; unused)
    const float* ew  = (const float*)d_in[3];
    const float* eb  = (const float*)d_in[4];
    const float* e1w = (const float*)d_in[5];
    const float* e1b = (const float*)d_in[6];
    const float* e2w = (const float*)d_in[7];
    const float* e2b = (const float*)d_in[8];
    const float* gw  = (const float*)d_in[9];
    const float* gb  = (const float*)d_in[10];
    const float* c1w = (const float*)d_in[11];
    const float* c1b = (const float*)d_in[12];
    const float* c2w = (const float*)d_in[13];
    const float* c2b = (const float*)d_in[14];
    const float* n1w = (const float*)d_in[15];
    const float* n1b = (const float*)d_in[16];
    const float* n2w = (const float*)d_in[17];
    const float* n2b = (const float*)d_in[18];
    const float* scl = (const float*)d_in[19];

    cudaMemcpyToSymbolAsync(g_coors, coor, BN*2*sizeof(float), 0,
                            cudaMemcpyDeviceToDevice, 0);

    // layer 0: knn(0) fused with embed+pre(0)
    embed_knn_kernel<<<BN, 256>>>(0, feat, ew, eb, e1w, e1b);
    edge_kernel<<<BN/4, 128>>>(0,
                             e1w, e2w, e2b, gw, gb, c1w, c1b, c2w, c2b, scl);

    // boundaries: node_pre(l) fused with knn(l+1)
    for (int l = 1; l < 3; l++){
        int npCur = (l-1) & 1;         // buffer the previous layer computed into
        int knnCur = l & 1;            // coords written by previous edge
        node_knn_kernel<<<BN, 256>>>(npCur, knnCur,
                                  n1w + (l-1)*64*64, n1b + (l-1)*64,
                                  n2w + (l-1)*64*DD, n2b + (l-1)*DD,
                                  e1w + l*65*EH, e1b + l*EH);
        edge_kernel<<<BN/4, 128>>>(knnCur,
                                 e1w + l*65*EH, e2w + l*EH*DD, e2b + l*DD,
                                 gw + l*DD, gb + l,
                                 c1w + l*DD*KK, c1b + l*KK,
                                 c2w + l*KK, c2b + l, scl + l);
    }

    // final node MLP -> d_out
    node_last_kernel<<<BN/2, 256>>>(0, (float*)d_out,
                              n1w + 2*64*64, n1b + 2*64,
                              n2w + 2*64*DD, n2b + 2*DD);
}